// round 15
// baseline (speedup 1.0000x reference)
#include <cuda_runtime.h>
#include <cuda_fp16.h>
#include <cstdint>

#define BB 4
#define SS 2048
#define HH 512
#define NHH 8
#define HDD 64
#define BSH (BB * SS * HH)
#define EXPC 0.18033688011112042f   // log2(e)/8

// Scratch (device globals: no allocation allowed in kernel_launch)
__device__ __half g_Wh[4u * HH * HH];         // fp16 copies of Wq,Wk,Wv,Wo
__device__ __half g_Qh[BSH];
__device__ __half g_Kh[BSH];
__device__ __half g_Vh[BSH];                  // V^T: [b][h][d][s]
__device__ __half g_Ch[BSH];                  // context

__device__ __forceinline__ float ex2(float x) {
    float y; asm("ex2.approx.ftz.f32 %0, %1;" : "=f"(y) : "f"(x)); return y;
}
__device__ __forceinline__ void cp16(unsigned dst, const void* src) {
    asm volatile("cp.async.cg.shared.global [%0], [%1], 16;" :: "r"(dst), "l"(src));
}
__device__ __forceinline__ void cp_commit() { asm volatile("cp.async.commit_group;"); }
__device__ __forceinline__ void cp_wait1() { asm volatile("cp.async.wait_group 1;"); }
__device__ __forceinline__ void cp_wait2() { asm volatile("cp.async.wait_group 2;"); }
__device__ __forceinline__ void cp_wait4() { asm volatile("cp.async.wait_group 4;"); }
__device__ __forceinline__ void cp_wait5() { asm volatile("cp.async.wait_group 5;"); }
__device__ __forceinline__ void cp_wait0() { asm volatile("cp.async.wait_group 0;"); }

__device__ __forceinline__ void mma_f16(float* c, const unsigned* a, const unsigned* b) {
    asm volatile(
        "mma.sync.aligned.m16n8k16.row.col.f32.f16.f16.f32 "
        "{%0,%1,%2,%3}, {%4,%5,%6,%7}, {%8,%9}, {%0,%1,%2,%3};"
        : "+f"(c[0]), "+f"(c[1]), "+f"(c[2]), "+f"(c[3])
        : "r"(a[0]), "r"(a[1]), "r"(a[2]), "r"(a[3]), "r"(b[0]), "r"(b[1]));
}
__device__ __forceinline__ void ldmx4(unsigned* r, unsigned addr) {
    asm volatile("ldmatrix.sync.aligned.m8n8.x4.shared.b16 {%0,%1,%2,%3}, [%4];"
                 : "=r"(r[0]), "=r"(r[1]), "=r"(r[2]), "=r"(r[3]) : "r"(addr));
}
__device__ __forceinline__ unsigned packh2(float lo, float hi) {
    __half2 h = __floats2half2_rn(lo, hi);
    return *(unsigned*)&h;
}

// ---------------------------------------------------------------------------
// weights fp32 -> fp16 (small: 4 MB total)
// ---------------------------------------------------------------------------
__global__ __launch_bounds__(256) void cvt_w(const float* __restrict__ w0,
                                             const float* __restrict__ w1,
                                             const float* __restrict__ w2,
                                             const float* __restrict__ w3,
                                             __half* __restrict__ dst)
{
    const float* s = blockIdx.y == 0 ? w0 : (blockIdx.y == 1 ? w1 :
                     (blockIdx.y == 2 ? w2 : w3));
    long long base = (long long)blockIdx.y * (HH * HH);
    int idx = (blockIdx.x * 256 + threadIdx.x) * 4;
    float4 x = *(const float4*)(s + idx);
    __half2 h0 = __floats2half2_rn(x.x, x.y);
    __half2 h1 = __floats2half2_rn(x.z, x.w);
    *(uint2*)(dst + base + idx) = make_uint2(*(unsigned*)&h0, *(unsigned*)&h1);
}

// ---------------------------------------------------------------------------
// merged Q/K/V projection: A fp32 (register-prefetched, converted during STS),
// W fp16 via cp.async. BM=BN=128, BK=32, 8 warps (2m x 4n) WM64 x WN32,
// 3-stage ring, one barrier. ldmatrix fragments.
// ---------------------------------------------------------------------------
#define GBUF 10240

__global__ __launch_bounds__(256, 2)
void qkv_gemm(const float* __restrict__ q, const float* __restrict__ k,
              const float* __restrict__ v, const __half* __restrict__ Wh,
              const float* __restrict__ bq, const float* __restrict__ bk,
              const float* __restrict__ bv,
              __half* __restrict__ Qh, __half* __restrict__ Kh,
              __half* __restrict__ Vh)
{
    __shared__ __align__(16) __half As[3][128][40];
    __shared__ __align__(16) __half Bs[3][128][40];

    const unsigned sa = (unsigned)__cvta_generic_to_shared(&As[0][0][0]);
    const unsigned sbb = (unsigned)__cvta_generic_to_shared(&Bs[0][0][0]);

    const int z = blockIdx.z;
    const int bm = blockIdx.y * 128;
    const int bn = blockIdx.x * 128;
    const int tid = threadIdx.x;
    const int warpId = tid >> 5, lane = tid & 31;
    const int g = lane >> 2, tg = lane & 3;
    const int wm = warpId >> 2;
    const int wn = warpId & 3;

    const float* A = z == 0 ? q : (z == 1 ? k : v);
    const __half* W = Wh + (long long)z * (HH * HH);
    const float* bias = z == 0 ? bq : (z == 1 ? bk : bv);

    float4 pr[4];
    auto prefA = [&](int kt) {
#pragma unroll
        for (int it = 0; it < 4; it++) {
            int idx = tid + it * 256;
            int row = idx >> 3, seg = idx & 7;
            pr[it] = *(const float4*)(A + (long long)(bm + row) * 512 + kt * 32 + seg * 4);
        }
    };
    auto stsA = [&](int buf) {
#pragma unroll
        for (int it = 0; it < 4; it++) {
            int idx = tid + it * 256;
            int row = idx >> 3, seg = idx & 7;
            __half2 h0 = __floats2half2_rn(pr[it].x, pr[it].y);
            __half2 h1 = __floats2half2_rn(pr[it].z, pr[it].w);
            *(uint2*)(&As[buf][row][seg * 4]) = make_uint2(*(unsigned*)&h0, *(unsigned*)&h1);
        }
    };
    auto cpW = [&](int kt, int buf) {
#pragma unroll
        for (int it = 0; it < 2; it++) {
            int idx = tid + it * 256;
            int row = idx >> 2, seg = idx & 3;
            cp16(sbb + buf * GBUF + row * 80 + seg * 16,
                 W + (long long)(bn + row) * 512 + kt * 32 + seg * 8);
        }
    };

    float c[4][4][4];
#pragma unroll
    for (int i = 0; i < 4; i++)
#pragma unroll
        for (int j = 0; j < 4; j++)
#pragma unroll
            for (int r = 0; r < 4; r++) c[i][j][r] = 0.0f;

    // prologue: tiles 0,1 blocking; tile 2 LDGs in flight
    prefA(0); stsA(0); cpW(0, 0); cp_commit();
    prefA(1); stsA(1); cpW(1, 1); cp_commit();
    prefA(2);

    const unsigned aoff = (lane & 15) * 80 + (lane >> 4) * 16;
    const unsigned boff = ((lane >> 4) * 8 + (lane & 7)) * 80 + ((lane >> 3) & 1) * 16;

    int buf = 0;
    for (int kt = 0; kt < 16; kt++) {
        cp_wait1();
        __syncthreads();
        int nb = buf + 2; if (nb >= 3) nb -= 3;
        if (kt < 14) { cpW(kt + 2, nb); cp_commit(); }

        const unsigned abase = sa + buf * GBUF;
        const unsigned bbase = sbb + buf * GBUF;
#pragma unroll
        for (int kc = 0; kc < 2; kc++) {
            unsigned a[4][4];
#pragma unroll
            for (int mt = 0; mt < 4; mt++)
                ldmx4(a[mt], abase + (wm * 64 + mt * 16) * 80 + kc * 32 + aoff);
#pragma unroll
            for (int np = 0; np < 2; np++) {
                unsigned bf[4];
                ldmx4(bf, bbase + (wn * 32 + np * 16) * 80 + kc * 32 + boff);
#pragma unroll
                for (int mt = 0; mt < 4; mt++) {
                    mma_f16(c[mt][2 * np],     a[mt], bf);
                    mma_f16(c[mt][2 * np + 1], a[mt], bf + 2);
                }
            }
        }

        if (kt < 14) stsA(nb);          // LDG data arrived during compute
        if (kt < 13) prefA(kt + 3);     // issue next prefetch
        if (++buf == 3) buf = 0;
    }

#pragma unroll
    for (int mt = 0; mt < 4; mt++) {
#pragma unroll
        for (int nt = 0; nt < 4; nt++) {
            int row = bm + wm * 64 + mt * 16 + g;
            int col = bn + wn * 32 + nt * 8 + 2 * tg;
            float bx = bias[col], by = bias[col + 1];
            float o0 = c[mt][nt][0] + bx, o1 = c[mt][nt][1] + by;
            float o2 = c[mt][nt][2] + bx, o3 = c[mt][nt][3] + by;
            if (z < 2) {
                __half* Ch = z == 0 ? Qh : Kh;
                *(__half2*)(Ch + (long long)row * 512 + col) = __floats2half2_rn(o0, o1);
                *(__half2*)(Ch + (long long)(row + 8) * 512 + col) = __floats2half2_rn(o2, o3);
            } else {
                int bo = row >> 11, so = row & 2047;
                int ho = col >> 6, dd = col & 63;
                long long base = (((long long)bo * NHH + ho) * HDD + dd) * SS + so;
                Vh[base]          = __float2half_rn(o0);
                Vh[base + SS]     = __float2half_rn(o1);
                Vh[base + 8]      = __float2half_rn(o2);
                Vh[base + SS + 8] = __float2half_rn(o3);
            }
        }
    }
}

// output projection: fp16 A -> fp32 out (3-stage ring, ldmatrix fragments)
__global__ __launch_bounds__(256, 2)
void out_gemm(const __half* __restrict__ A, const __half* __restrict__ W,
              const float* __restrict__ bias, float* __restrict__ Cout)
{
    __shared__ __align__(16) __half As[3][128][40];
    __shared__ __align__(16) __half Bs[3][128][40];

    const unsigned sa = (unsigned)__cvta_generic_to_shared(&As[0][0][0]);
    const unsigned sbb = (unsigned)__cvta_generic_to_shared(&Bs[0][0][0]);

    const int bm = blockIdx.y * 128;
    const int bn = blockIdx.x * 128;
    const int tid = threadIdx.x;
    const int warpId = tid >> 5, lane = tid & 31;
    const int g = lane >> 2, tg = lane & 3;
    const int wm = warpId >> 2;
    const int wn = warpId & 3;

    auto stage = [&](int kt, int buf) {
#pragma unroll
        for (int it = 0; it < 2; it++) {
            int idx = tid + it * 256;
            int row = idx >> 2, seg = idx & 3;
            cp16(sa + buf * GBUF + row * 80 + seg * 16,
                 A + (long long)(bm + row) * 512 + kt * 32 + seg * 8);
            cp16(sbb + buf * GBUF + row * 80 + seg * 16,
                 W + (long long)(bn + row) * 512 + kt * 32 + seg * 8);
        }
    };

    float c[4][4][4];
#pragma unroll
    for (int i = 0; i < 4; i++)
#pragma unroll
        for (int j = 0; j < 4; j++)
#pragma unroll
            for (int r = 0; r < 4; r++) c[i][j][r] = 0.0f;

    stage(0, 0); cp_commit();
    stage(1, 1); cp_commit();

    const unsigned aoff = (lane & 15) * 80 + (lane >> 4) * 16;
    const unsigned boff = ((lane >> 4) * 8 + (lane & 7)) * 80 + ((lane >> 3) & 1) * 16;

    int buf = 0;
    for (int kt = 0; kt < 16; kt++) {
        cp_wait1();
        __syncthreads();
        if (kt < 14) {
            int nb = buf + 2; if (nb >= 3) nb -= 3;
            stage(kt + 2, nb);
            cp_commit();
        }

        const unsigned abase = sa + buf * GBUF;
        const unsigned bbase = sbb + buf * GBUF;
#pragma unroll
        for (int kc = 0; kc < 2; kc++) {
            unsigned a[4][4];
#pragma unroll
            for (int mt = 0; mt < 4; mt++)
                ldmx4(a[mt], abase + (wm * 64 + mt * 16) * 80 + kc * 32 + aoff);
#pragma unroll
            for (int np = 0; np < 2; np++) {
                unsigned bf[4];
                ldmx4(bf, bbase + (wn * 32 + np * 16) * 80 + kc * 32 + boff);
#pragma unroll
                for (int mt = 0; mt < 4; mt++) {
                    mma_f16(c[mt][2 * np],     a[mt], bf);
                    mma_f16(c[mt][2 * np + 1], a[mt], bf + 2);
                }
            }
        }
        if (++buf == 3) buf = 0;
    }

#pragma unroll
    for (int mt = 0; mt < 4; mt++) {
#pragma unroll
        for (int nt = 0; nt < 4; nt++) {
            int row = bm + wm * 64 + mt * 16 + g;
            int col = bn + wn * 32 + nt * 8 + 2 * tg;
            float bx = bias[col], by = bias[col + 1];
            *(float2*)(Cout + (long long)row * 512 + col) =
                make_float2(c[mt][nt][0] + bx, c[mt][nt][1] + by);
            *(float2*)(Cout + (long long)(row + 8) * 512 + col) =
                make_float2(c[mt][nt][2] + bx, c[mt][nt][3] + by);
        }
    }
}

// ---------------------------------------------------------------------------
// Fused attention, BOTH passes in one kernel. 256 threads (8 warps), Q tile =
// 256 rows (32/warp, MT=2), 64-row K/V tiles. Pass1: 6-deep K ring. Pass2:
// 4-deep K + 4-deep V rings, staged 3 ahead (wait_group 2). One sync/tile.
// smem: Q 36864 | K 4*9216 | V 4*9216 = 110592 bytes (pass1 ring spans K+V).
// ---------------------------------------------------------------------------
#define QOFF 0
#define KOFF 36864
#define VOFF 73728
#define F_SMEM 110592

__global__ __launch_bounds__(256, 2)
void attn_fused(const __half* __restrict__ Q, const __half* __restrict__ K,
                const __half* __restrict__ V,
                float* __restrict__ attn, __half* __restrict__ Cx)
{
    extern __shared__ __align__(16) unsigned char smraw[];
    const unsigned sb = (unsigned)__cvta_generic_to_shared(smraw);

    const int tid = threadIdx.x;
    const int wid = tid >> 5, lane = tid & 31;
    const int g = lane >> 2, tg = lane & 3;
    const int wrow = wid * 32;

    const int qt = blockIdx.x, bh = blockIdx.y;
    const int b = bh >> 3, h = bh & 7;

    const __half* Qg = Q + ((long long)b * SS + qt * 256) * HH + h * HDD;
    const __half* Kg = K + (long long)b * SS * HH + h * HDD;
    const __half* Vg = V + (long long)bh * HDD * SS;

    auto stageK = [&](int t, int buf) {
#pragma unroll
        for (int i = 0; i < 2; i++) {
            int idx = tid + i * 256;
            int row = idx >> 3, seg = idx & 7;
            cp16(sb + KOFF + buf * 9216 + row * 144 + seg * 16,
                 Kg + (long long)(t * 64 + row) * HH + seg * 8);
        }
    };
    auto stageV = [&](int t, int buf) {
#pragma unroll
        for (int i = 0; i < 2; i++) {
            int idx = tid + i * 256;
            int row = idx >> 3, seg = idx & 7;
            cp16(sb + VOFF + buf * 9216 + row * 144 + seg * 16,
                 Vg + (long long)row * SS + t * 64 + seg * 8);
        }
    };

    // ---- prologue: Q+K0 | K1 | K2 | K3 | K4 (pass1 6-deep ring) ----
#pragma unroll
    for (int i = 0; i < 8; i++) {
        int idx = tid + i * 256;
        int row = idx >> 3, seg = idx & 7;
        cp16(sb + QOFF + row * 144 + seg * 16, Qg + (long long)row * HH + seg * 8);
    }
    stageK(0, 0);
    cp_commit();
    stageK(1, 1); cp_commit();
    stageK(2, 2); cp_commit();
    stageK(3, 3); cp_commit();
    stageK(4, 4); cp_commit();

    cp_wait4();            // group 0 (Q + K0) complete
    __syncthreads();

    // persistent Q A-fragments (used by BOTH passes)
    const unsigned qloff = (lane & 15) * 144 + (lane >> 4) * 16;
    unsigned aq[2][4][4];
#pragma unroll
    for (int mt = 0; mt < 2; mt++)
#pragma unroll
        for (int kc = 0; kc < 4; kc++)
            ldmx4(aq[mt][kc], sb + QOFF + (wrow + mt * 16) * 144 + kc * 32 + qloff);

    const unsigned loff = ((lane >> 4) * 8 + (lane & 7)) * 144 + ((lane >> 3) & 1) * 16;

    // ================= pass 1: l[row] = sum exp2(s*EXPC), 6-deep ring =======
    float l[2][2] = {{0.0f, 0.0f}, {0.0f, 0.0f}};

    for (int t = 0; t < 32; t++) {
        if (t > 0) __syncthreads();
        if (t < 27) {
            int nb = t + 5; nb -= (nb / 6) * 6;
            stageK(t + 5, nb);
        }
        cp_commit();
        cp_wait5();

        const unsigned kb = sb + KOFF + (t % 6) * 9216;
#pragma unroll
        for (int ch = 0; ch < 4; ch++) {
            float s[2][2][4];
#pragma unroll
            for (int mt = 0; mt < 2; mt++)
#pragma unroll
                for (int j = 0; j < 2; j++)
#pragma unroll
                    for (int r = 0; r < 4; r++) s[mt][j][r] = 0.0f;
#pragma unroll
            for (int kc = 0; kc < 4; kc++) {
                unsigned kf[4];
                ldmx4(kf, kb + ch * 2304 + kc * 32 + loff);
                mma_f16(s[0][0], aq[0][kc], kf);
                mma_f16(s[0][1], aq[0][kc], kf + 2);
                mma_f16(s[1][0], aq[1][kc], kf);
                mma_f16(s[1][1], aq[1][kc], kf + 2);
            }
#pragma unroll
            for (int mt = 0; mt < 2; mt++)
#pragma unroll
                for (int j = 0; j < 2; j++) {
                    l[mt][0] += ex2(s[mt][j][0] * EXPC) + ex2(s[mt][j][1] * EXPC);
                    l[mt][1] += ex2(s[mt][j][2] * EXPC) + ex2(s[mt][j][3] * EXPC);
                }
        }
    }

    // quad reduce -> li (registers only)
    float li[2][2];
#pragma unroll
    for (int mt = 0; mt < 2; mt++)
#pragma unroll
        for (int hh = 0; hh < 2; hh++) {
            float v = l[mt][hh];
            v += __shfl_xor_sync(0xffffffffu, v, 1);
            v += __shfl_xor_sync(0xffffffffu, v, 2);
            li[mt][hh] = -__log2f(v);
        }

    // ---- transition: drain, prime pass2's 4-deep K/V rings ----
    cp_wait0();
    __syncthreads();
    stageK(0, 0); stageV(0, 0); cp_commit();
    stageK(1, 1); stageV(1, 1); cp_commit();
    stageK(2, 2); stageV(2, 2); cp_commit();
    cp_wait2();
    __syncthreads();

    // ================= pass 2: p -> attn; O += P*V =================
    float o[2][8][4];
#pragma unroll
    for (int mt = 0; mt < 2; mt++)
#pragma unroll
        for (int nt = 0; nt < 8; nt++)
#pragma unroll
            for (int r = 0; r < 4; r++) o[mt][nt][r] = 0.0f;

    float* attnBase = attn + ((long long)bh * SS + qt * 256 + wrow + g) * SS;

    for (int t = 0; t < 32; t++) {
        if (t > 0) __syncthreads();
        if (t < 29) {
            int nb = (t + 3) & 3;
            stageK(t + 3, nb); stageV(t + 3, nb);
        }
        cp_commit();
        cp_wait2();

        const unsigned kb = sb + KOFF + (t & 3) * 9216;
        const unsigned vb = sb + VOFF + (t & 3) * 9216;

#pragma unroll
        for (int ch = 0; ch < 4; ch++) {
            float s[2][2][4];
#pragma unroll
            for (int mt = 0; mt < 2; mt++)
#pragma unroll
                for (int j = 0; j < 2; j++)
#pragma unroll
                    for (int r = 0; r < 4; r++) s[mt][j][r] = 0.0f;
#pragma unroll
            for (int kc = 0; kc < 4; kc++) {
                unsigned kf[4];
                ldmx4(kf, kb + ch * 2304 + kc * 32 + loff);
                mma_f16(s[0][0], aq[0][kc], kf);
                mma_f16(s[0][1], aq[0][kc], kf + 2);
                mma_f16(s[1][0], aq[1][kc], kf);
                mma_f16(s[1][1], aq[1][kc], kf + 2);
            }

            unsigned pa[2][4];
#pragma unroll
            for (int mt = 0; mt < 2; mt++) {
#pragma unroll
                for (int j = 0; j < 2; j++) {
                    s[mt][j][0] = ex2(fmaf(s[mt][j][0], EXPC, li[mt][0]));
                    s[mt][j][1] = ex2(fmaf(s[mt][j][1], EXPC, li[mt][0]));
                    s[mt][j][2] = ex2(fmaf(s[mt][j][2], EXPC, li[mt][1]));
                    s[mt][j][3] = ex2(fmaf(s[mt][j][3], EXPC, li[mt][1]));
                }
                pa[mt][0] = packh2(s[mt][0][0], s[mt][0][1]);
                pa[mt][1] = packh2(s[mt][0][2], s[mt][0][3]);
                pa[mt][2] = packh2(s[mt][1][0], s[mt][1][1]);
                pa[mt][3] = packh2(s[mt][1][2], s[mt][1][3]);
                float* ap = attnBase + (long long)(mt * 16) * SS + t * 64 + ch * 16 + 2 * tg;
                asm volatile("st.global.cs.v2.f32 [%0], {%1,%2};"
                             :: "l"(ap), "f"(s[mt][0][0]), "f"(s[mt][0][1]));
                asm volatile("st.global.cs.v2.f32 [%0], {%1,%2};"
                             :: "l"(ap + 8), "f"(s[mt][1][0]), "f"(s[mt][1][1]));
                asm volatile("st.global.cs.v2.f32 [%0], {%1,%2};"
                             :: "l"(ap + 8LL * SS), "f"(s[mt][0][2]), "f"(s[mt][0][3]));
                asm volatile("st.global.cs.v2.f32 [%0], {%1,%2};"
                             :: "l"(ap + 8LL * SS + 8), "f"(s[mt][1][2]), "f"(s[mt][1][3]));
            }

#pragma unroll
            for (int np = 0; np < 4; np++) {
                unsigned vf[4];
                ldmx4(vf, vb + np * 2304 + ch * 32 + loff);
                mma_f16(o[0][2 * np],     pa[0], vf);
                mma_f16(o[0][2 * np + 1], pa[0], vf + 2);
                mma_f16(o[1][2 * np],     pa[1], vf);
                mma_f16(o[1][2 * np + 1], pa[1], vf + 2);
            }
        }
    }

    __half* Cp = Cx + ((long long)b * SS + qt * 256 + wrow + g) * HH + h * HDD;
#pragma unroll
    for (int mt = 0; mt < 2; mt++)
#pragma unroll
        for (int nt = 0; nt < 8; nt++) {
            int col = nt * 8 + 2 * tg;
            *(__half2*)(Cp + (long long)(mt * 16) * HH + col) =
                __floats2half2_rn(o[mt][nt][0], o[mt][nt][1]);
            *(__half2*)(Cp + (long long)(mt * 16 + 8) * HH + col) =
                __floats2half2_rn(o[mt][nt][2], o[mt][nt][3]);
        }
}

// ---------------------------------------------------------------------------
extern "C" void kernel_launch(void* const* d_in, const int* in_sizes, int n_in,
                              void* d_out, int out_size)
{
    const float* query  = (const float*)d_in[0];
    const float* key_in = (const float*)d_in[1];
    const float* value  = (const float*)d_in[2];
    const float* Wq = (const float*)d_in[3];
    const float* bq = (const float*)d_in[4];
    const float* Wk = (const float*)d_in[5];
    const float* bk = (const float*)d_in[6];
    const float* Wv = (const float*)d_in[7];
    const float* bv = (const float*)d_in[8];
    const float* Wo = (const float*)d_in[9];
    const float* bo = (const float*)d_in[10];

    float* out  = (float*)d_out;
    float* attn = out + (long long)BSH;

    __half *Wh, *Qh, *Kh, *Vh, *Ch;
    cudaGetSymbolAddress((void**)&Wh, g_Wh);
    cudaGetSymbolAddress((void**)&Qh, g_Qh);
    cudaGetSymbolAddress((void**)&Kh, g_Kh);
    cudaGetSymbolAddress((void**)&Vh, g_Vh);
    cudaGetSymbolAddress((void**)&Ch, g_Ch);

    cudaFuncSetAttribute(attn_fused, cudaFuncAttributeMaxDynamicSharedMemorySize, F_SMEM);

    // weights fp32 -> fp16 (inputs converted inline inside qkv_gemm)
    cvt_w<<<dim3(256, 4), 256>>>(Wq, Wk, Wv, Wo, Wh);

    // merged Q/K/V projections
    qkv_gemm<<<dim3(4, 64, 3), 256>>>(query, key_in, value, Wh,
                                      bq, bk, bv, Qh, Kh, Vh);

    // fused attention (both passes, one kernel)
    attn_fused<<<dim3(SS / 256, BB * NHH), 256, F_SMEM>>>(Qh, Kh, Vh, attn, Ch);

    // output projection
    out_gemm<<<dim3(4, 64), 256>>>(Ch, Wh + 3u * HH * HH, bo, out);
}

// round 16
// speedup vs baseline: 1.0157x; 1.0157x over previous
#include <cuda_runtime.h>
#include <cuda_fp16.h>
#include <cstdint>

#define BB 4
#define SS 2048
#define HH 512
#define NHH 8
#define HDD 64
#define BSH (BB * SS * HH)
#define EXPC 0.18033688011112042f   // log2(e)/8

// Scratch (device globals: no allocation allowed in kernel_launch)
__device__ __half g_Wh[4u * HH * HH];         // fp16 copies of Wq,Wk,Wv,Wo
__device__ __half g_Qh[BSH];
__device__ __half g_Kh[BSH];
__device__ __half g_Vh[BSH];                  // V^T: [b][h][d][s]
__device__ __half g_Ch[BSH];                  // context

__device__ __forceinline__ float ex2(float x) {
    float y; asm("ex2.approx.ftz.f32 %0, %1;" : "=f"(y) : "f"(x)); return y;
}
__device__ __forceinline__ void cp16(unsigned dst, const void* src) {
    asm volatile("cp.async.cg.shared.global [%0], [%1], 16;" :: "r"(dst), "l"(src));
}
__device__ __forceinline__ void cp_commit() { asm volatile("cp.async.commit_group;"); }
__device__ __forceinline__ void cp_wait1() { asm volatile("cp.async.wait_group 1;"); }
__device__ __forceinline__ void cp_wait2() { asm volatile("cp.async.wait_group 2;"); }
__device__ __forceinline__ void cp_wait0() { asm volatile("cp.async.wait_group 0;"); }

__device__ __forceinline__ void mma_f16(float* c, const unsigned* a, const unsigned* b) {
    asm volatile(
        "mma.sync.aligned.m16n8k16.row.col.f32.f16.f16.f32 "
        "{%0,%1,%2,%3}, {%4,%5,%6,%7}, {%8,%9}, {%0,%1,%2,%3};"
        : "+f"(c[0]), "+f"(c[1]), "+f"(c[2]), "+f"(c[3])
        : "r"(a[0]), "r"(a[1]), "r"(a[2]), "r"(a[3]), "r"(b[0]), "r"(b[1]));
}
__device__ __forceinline__ void ldmx4(unsigned* r, unsigned addr) {
    asm volatile("ldmatrix.sync.aligned.m8n8.x4.shared.b16 {%0,%1,%2,%3}, [%4];"
                 : "=r"(r[0]), "=r"(r[1]), "=r"(r[2]), "=r"(r[3]) : "r"(addr));
}
__device__ __forceinline__ unsigned packh2(float lo, float hi) {
    __half2 h = __floats2half2_rn(lo, hi);
    return *(unsigned*)&h;
}

// ---------------------------------------------------------------------------
// weights fp32 -> fp16 (small: 4 MB total)
// ---------------------------------------------------------------------------
__global__ __launch_bounds__(256) void cvt_w(const float* __restrict__ w0,
                                             const float* __restrict__ w1,
                                             const float* __restrict__ w2,
                                             const float* __restrict__ w3,
                                             __half* __restrict__ dst)
{
    const float* s = blockIdx.y == 0 ? w0 : (blockIdx.y == 1 ? w1 :
                     (blockIdx.y == 2 ? w2 : w3));
    long long base = (long long)blockIdx.y * (HH * HH);
    int idx = (blockIdx.x * 256 + threadIdx.x) * 4;
    float4 x = *(const float4*)(s + idx);
    __half2 h0 = __floats2half2_rn(x.x, x.y);
    __half2 h1 = __floats2half2_rn(x.z, x.w);
    *(uint2*)(dst + base + idx) = make_uint2(*(unsigned*)&h0, *(unsigned*)&h1);
}

// ---------------------------------------------------------------------------
// merged Q/K/V projection: A fp32 (converted during staging), W fp16 cp.async.
// BM=BN=128, BK=32, 8 warps (2m x 4n) WM64 x WN32, 3-stage ring, one barrier.
// Fragment loads via ldmatrix.x4 (stride 80B: conflict-free).
// ---------------------------------------------------------------------------
#define GBUF 10240

__global__ __launch_bounds__(256, 2)
void qkv_gemm(const float* __restrict__ q, const float* __restrict__ k,
              const float* __restrict__ v, const __half* __restrict__ Wh,
              const float* __restrict__ bq, const float* __restrict__ bk,
              const float* __restrict__ bv,
              __half* __restrict__ Qh, __half* __restrict__ Kh,
              __half* __restrict__ Vh)
{
    __shared__ __align__(16) __half As[3][128][40];
    __shared__ __align__(16) __half Bs[3][128][40];

    const unsigned sa = (unsigned)__cvta_generic_to_shared(&As[0][0][0]);
    const unsigned sbb = (unsigned)__cvta_generic_to_shared(&Bs[0][0][0]);

    const int z = blockIdx.z;
    const int bm = blockIdx.y * 128;
    const int bn = blockIdx.x * 128;
    const int tid = threadIdx.x;
    const int warpId = tid >> 5, lane = tid & 31;
    const int g = lane >> 2, tg = lane & 3;
    const int wm = warpId >> 2;
    const int wn = warpId & 3;

    const float* A = z == 0 ? q : (z == 1 ? k : v);
    const __half* W = Wh + (long long)z * (HH * HH);
    const float* bias = z == 0 ? bq : (z == 1 ? bk : bv);

    auto stage = [&](int kt, int buf) {
        // A: fp32 -> fp16 inline
#pragma unroll
        for (int it = 0; it < 4; it++) {
            int idx = tid + it * 256;
            int row = idx >> 3, seg = idx & 7;
            float4 x = *(const float4*)(A + (long long)(bm + row) * 512 + kt * 32 + seg * 4);
            __half2 h0 = __floats2half2_rn(x.x, x.y);
            __half2 h1 = __floats2half2_rn(x.z, x.w);
            *(uint2*)(&As[buf][row][seg * 4]) = make_uint2(*(unsigned*)&h0, *(unsigned*)&h1);
        }
        // W: fp16 cp.async
#pragma unroll
        for (int it = 0; it < 2; it++) {
            int idx = tid + it * 256;
            int row = idx >> 2, seg = idx & 3;
            cp16(sbb + buf * GBUF + row * 80 + seg * 16,
                 W + (long long)(bn + row) * 512 + kt * 32 + seg * 8);
        }
    };

    float c[4][4][4];
#pragma unroll
    for (int i = 0; i < 4; i++)
#pragma unroll
        for (int j = 0; j < 4; j++)
#pragma unroll
            for (int r = 0; r < 4; r++) c[i][j][r] = 0.0f;

    stage(0, 0); cp_commit();
    stage(1, 1); cp_commit();

    const unsigned aoff = (lane & 15) * 80 + (lane >> 4) * 16;
    const unsigned boff = ((lane >> 4) * 8 + (lane & 7)) * 80 + ((lane >> 3) & 1) * 16;

    int buf = 0;
    for (int kt = 0; kt < 16; kt++) {
        cp_wait1();
        __syncthreads();
        if (kt < 14) {
            int nb = buf + 2; if (nb >= 3) nb -= 3;
            stage(kt + 2, nb);
            cp_commit();
        }

        const unsigned abase = sa + buf * GBUF;
        const unsigned bbase = sbb + buf * GBUF;
#pragma unroll
        for (int kc = 0; kc < 2; kc++) {
            unsigned a[4][4];
#pragma unroll
            for (int mt = 0; mt < 4; mt++)
                ldmx4(a[mt], abase + (wm * 64 + mt * 16) * 80 + kc * 32 + aoff);
#pragma unroll
            for (int np = 0; np < 2; np++) {
                unsigned bf[4];
                ldmx4(bf, bbase + (wn * 32 + np * 16) * 80 + kc * 32 + boff);
#pragma unroll
                for (int mt = 0; mt < 4; mt++) {
                    mma_f16(c[mt][2 * np],     a[mt], bf);
                    mma_f16(c[mt][2 * np + 1], a[mt], bf + 2);
                }
            }
        }
        if (++buf == 3) buf = 0;
    }

#pragma unroll
    for (int mt = 0; mt < 4; mt++) {
#pragma unroll
        for (int nt = 0; nt < 4; nt++) {
            int row = bm + wm * 64 + mt * 16 + g;
            int col = bn + wn * 32 + nt * 8 + 2 * tg;
            float bx = bias[col], by = bias[col + 1];
            float o0 = c[mt][nt][0] + bx, o1 = c[mt][nt][1] + by;
            float o2 = c[mt][nt][2] + bx, o3 = c[mt][nt][3] + by;
            if (z < 2) {
                __half* Ch = z == 0 ? Qh : Kh;
                *(__half2*)(Ch + (long long)row * 512 + col) = __floats2half2_rn(o0, o1);
                *(__half2*)(Ch + (long long)(row + 8) * 512 + col) = __floats2half2_rn(o2, o3);
            } else {
                int bo = row >> 11, so = row & 2047;
                int ho = col >> 6, dd = col & 63;
                long long base = (((long long)bo * NHH + ho) * HDD + dd) * SS + so;
                Vh[base]          = __float2half_rn(o0);
                Vh[base + SS]     = __float2half_rn(o1);
                Vh[base + 8]      = __float2half_rn(o2);
                Vh[base + SS + 8] = __float2half_rn(o3);
            }
        }
    }
}

// output projection: fp16 A -> fp32 out (3-stage ring, ldmatrix fragments)
__global__ __launch_bounds__(256, 2)
void out_gemm(const __half* __restrict__ A, const __half* __restrict__ W,
              const float* __restrict__ bias, float* __restrict__ Cout)
{
    __shared__ __align__(16) __half As[3][128][40];
    __shared__ __align__(16) __half Bs[3][128][40];

    const unsigned sa = (unsigned)__cvta_generic_to_shared(&As[0][0][0]);
    const unsigned sbb = (unsigned)__cvta_generic_to_shared(&Bs[0][0][0]);

    const int bm = blockIdx.y * 128;
    const int bn = blockIdx.x * 128;
    const int tid = threadIdx.x;
    const int warpId = tid >> 5, lane = tid & 31;
    const int g = lane >> 2, tg = lane & 3;
    const int wm = warpId >> 2;
    const int wn = warpId & 3;

    auto stage = [&](int kt, int buf) {
#pragma unroll
        for (int it = 0; it < 2; it++) {
            int idx = tid + it * 256;
            int row = idx >> 2, seg = idx & 3;
            cp16(sa + buf * GBUF + row * 80 + seg * 16,
                 A + (long long)(bm + row) * 512 + kt * 32 + seg * 8);
            cp16(sbb + buf * GBUF + row * 80 + seg * 16,
                 W + (long long)(bn + row) * 512 + kt * 32 + seg * 8);
        }
    };

    float c[4][4][4];
#pragma unroll
    for (int i = 0; i < 4; i++)
#pragma unroll
        for (int j = 0; j < 4; j++)
#pragma unroll
            for (int r = 0; r < 4; r++) c[i][j][r] = 0.0f;

    stage(0, 0); cp_commit();
    stage(1, 1); cp_commit();

    const unsigned aoff = (lane & 15) * 80 + (lane >> 4) * 16;
    const unsigned boff = ((lane >> 4) * 8 + (lane & 7)) * 80 + ((lane >> 3) & 1) * 16;

    int buf = 0;
    for (int kt = 0; kt < 16; kt++) {
        cp_wait1();
        __syncthreads();
        if (kt < 14) {
            int nb = buf + 2; if (nb >= 3) nb -= 3;
            stage(kt + 2, nb);
            cp_commit();
        }

        const unsigned abase = sa + buf * GBUF;
        const unsigned bbase = sbb + buf * GBUF;
#pragma unroll
        for (int kc = 0; kc < 2; kc++) {
            unsigned a[4][4];
#pragma unroll
            for (int mt = 0; mt < 4; mt++)
                ldmx4(a[mt], abase + (wm * 64 + mt * 16) * 80 + kc * 32 + aoff);
#pragma unroll
            for (int np = 0; np < 2; np++) {
                unsigned bf[4];
                ldmx4(bf, bbase + (wn * 32 + np * 16) * 80 + kc * 32 + boff);
#pragma unroll
                for (int mt = 0; mt < 4; mt++) {
                    mma_f16(c[mt][2 * np],     a[mt], bf);
                    mma_f16(c[mt][2 * np + 1], a[mt], bf + 2);
                }
            }
        }
        if (++buf == 3) buf = 0;
    }

#pragma unroll
    for (int mt = 0; mt < 4; mt++) {
#pragma unroll
        for (int nt = 0; nt < 4; nt++) {
            int row = bm + wm * 64 + mt * 16 + g;
            int col = bn + wn * 32 + nt * 8 + 2 * tg;
            float bx = bias[col], by = bias[col + 1];
            *(float2*)(Cout + (long long)row * 512 + col) =
                make_float2(c[mt][nt][0] + bx, c[mt][nt][1] + by);
            *(float2*)(Cout + (long long)(row + 8) * 512 + col) =
                make_float2(c[mt][nt][2] + bx, c[mt][nt][3] + by);
        }
    }
}

// ---------------------------------------------------------------------------
// Fused attention, BOTH passes in one kernel. 256 threads (8 warps), Q tile =
// 256 rows (32/warp, MT=2), 64-row K/V tiles.
// Pass1: 6-deep K ring, TWO tiles per barrier, wait-before-sync (race-free).
// Pass2: 3-deep K + V rings, one wait1+sync per tile (R14 structure).
// smem: Q 36864 | rings 6*9216 = 92160 bytes.
// ---------------------------------------------------------------------------
#define QOFF 0
#define KOFF 36864
#define VOFF 64512
#define F_SMEM 92160

__global__ __launch_bounds__(256, 2)
void attn_fused(const __half* __restrict__ Q, const __half* __restrict__ K,
                const __half* __restrict__ V,
                float* __restrict__ attn, __half* __restrict__ Cx)
{
    extern __shared__ __align__(16) unsigned char smraw[];
    const unsigned sb = (unsigned)__cvta_generic_to_shared(smraw);

    const int tid = threadIdx.x;
    const int wid = tid >> 5, lane = tid & 31;
    const int g = lane >> 2, tg = lane & 3;
    const int wrow = wid * 32;

    const int qt = blockIdx.x, bh = blockIdx.y;
    const int b = bh >> 3, h = bh & 7;

    const __half* Qg = Q + ((long long)b * SS + qt * 256) * HH + h * HDD;
    const __half* Kg = K + (long long)b * SS * HH + h * HDD;
    const __half* Vg = V + (long long)bh * HDD * SS;

    auto stageK = [&](int t, int buf) {
#pragma unroll
        for (int i = 0; i < 2; i++) {
            int idx = tid + i * 256;
            int row = idx >> 3, seg = idx & 7;
            cp16(sb + KOFF + buf * 9216 + row * 144 + seg * 16,
                 Kg + (long long)(t * 64 + row) * HH + seg * 8);
        }
    };
    auto stageV = [&](int t, int buf) {
#pragma unroll
        for (int i = 0; i < 2; i++) {
            int idx = tid + i * 256;
            int row = idx >> 3, seg = idx & 7;
            cp16(sb + VOFF + buf * 9216 + row * 144 + seg * 16,
                 Vg + (long long)row * SS + t * 64 + seg * 8);
        }
    };

    // ---- prologue: Q+K0 | K1 | K2 | K3 (4 groups) ----
#pragma unroll
    for (int i = 0; i < 8; i++) {
        int idx = tid + i * 256;
        int row = idx >> 3, seg = idx & 7;
        cp16(sb + QOFF + row * 144 + seg * 16, Qg + (long long)row * HH + seg * 8);
    }
    stageK(0, 0);
    cp_commit();
    stageK(1, 1); cp_commit();
    stageK(2, 2); cp_commit();
    stageK(3, 3); cp_commit();

    cp_wait2();            // Q+K0, K1 complete (K2,K3 may still fly)
    __syncthreads();       // visibility across threads

    // persistent Q A-fragments (used by BOTH passes)
    const unsigned qloff = (lane & 15) * 144 + (lane >> 4) * 16;
    unsigned aq[2][4][4];
#pragma unroll
    for (int mt = 0; mt < 2; mt++)
#pragma unroll
        for (int kc = 0; kc < 4; kc++)
            ldmx4(aq[mt][kc], sb + QOFF + (wrow + mt * 16) * 144 + kc * 32 + qloff);

    const unsigned loff = ((lane >> 4) * 8 + (lane & 7)) * 144 + ((lane >> 3) & 1) * 16;

    // ===== pass 1: l[row] = sum exp2(s*EXPC); 2 tiles per barrier =====
    float l[2][2] = {{0.0f, 0.0f}, {0.0f, 0.0f}};

    for (int tt = 0; tt < 16; tt++) {
        const int t0 = tt * 2;
        if (tt > 0) {
            cp_wait2();        // tiles t0, t0+1 complete (t0+2,t0+3 in flight)
            __syncthreads();   // visibility + protects bufs staged below
        }
        // stage tiles t0+4, t0+5 into bufs freed in previous iteration
        if (t0 + 4 < 32) stageK(t0 + 4, (t0 + 4) % 6);
        cp_commit();
        if (t0 + 5 < 32) stageK(t0 + 5, (t0 + 5) % 6);
        cp_commit();

#pragma unroll
        for (int u = 0; u < 2; u++) {
            const int t = t0 + u;
            const unsigned kb = sb + KOFF + (t % 6) * 9216;
#pragma unroll
            for (int ch = 0; ch < 4; ch++) {
                float s[2][2][4];
#pragma unroll
                for (int mt = 0; mt < 2; mt++)
#pragma unroll
                    for (int j = 0; j < 2; j++)
#pragma unroll
                        for (int r = 0; r < 4; r++) s[mt][j][r] = 0.0f;
#pragma unroll
                for (int kc = 0; kc < 4; kc++) {
                    unsigned kf[4];
                    ldmx4(kf, kb + ch * 2304 + kc * 32 + loff);
                    mma_f16(s[0][0], aq[0][kc], kf);
                    mma_f16(s[0][1], aq[0][kc], kf + 2);
                    mma_f16(s[1][0], aq[1][kc], kf);
                    mma_f16(s[1][1], aq[1][kc], kf + 2);
                }
#pragma unroll
                for (int mt = 0; mt < 2; mt++)
#pragma unroll
                    for (int j = 0; j < 2; j++) {
                        l[mt][0] += ex2(s[mt][j][0] * EXPC) + ex2(s[mt][j][1] * EXPC);
                        l[mt][1] += ex2(s[mt][j][2] * EXPC) + ex2(s[mt][j][3] * EXPC);
                    }
            }
        }
    }

    // quad reduce -> li (registers only)
    float li[2][2];
#pragma unroll
    for (int mt = 0; mt < 2; mt++)
#pragma unroll
        for (int hh = 0; hh < 2; hh++) {
            float v = l[mt][hh];
            v += __shfl_xor_sync(0xffffffffu, v, 1);
            v += __shfl_xor_sync(0xffffffffu, v, 2);
            li[mt][hh] = -__log2f(v);
        }

    // ---- transition: drain, re-prime K/V rings ----
    cp_wait0();
    __syncthreads();
    stageK(0, 0); stageV(0, 0);
    cp_commit();
    stageK(1, 1); stageV(1, 1);
    cp_commit();
    cp_wait1();
    __syncthreads();

    // ================= pass 2: p -> attn; O += P*V =================
    float o[2][8][4];
#pragma unroll
    for (int mt = 0; mt < 2; mt++)
#pragma unroll
        for (int nt = 0; nt < 8; nt++)
#pragma unroll
            for (int r = 0; r < 4; r++) o[mt][nt][r] = 0.0f;

    float* attnBase = attn + ((long long)bh * SS + qt * 256 + wrow + g) * SS;

    int buf = 0;
    for (int t = 0; t < 32; t++) {
        if (t > 0) { cp_wait1(); __syncthreads(); }
        if (t < 30) {
            int nb = buf + 2; if (nb >= 3) nb -= 3;
            stageK(t + 2, nb); stageV(t + 2, nb);
        }
        cp_commit();

        const unsigned kb = sb + KOFF + buf * 9216;
        const unsigned vb = sb + VOFF + buf * 9216;

#pragma unroll
        for (int ch = 0; ch < 4; ch++) {
            float s[2][2][4];
#pragma unroll
            for (int mt = 0; mt < 2; mt++)
#pragma unroll
                for (int j = 0; j < 2; j++)
#pragma unroll
                    for (int r = 0; r < 4; r++) s[mt][j][r] = 0.0f;
#pragma unroll
            for (int kc = 0; kc < 4; kc++) {
                unsigned kf[4];
                ldmx4(kf, kb + ch * 2304 + kc * 32 + loff);
                mma_f16(s[0][0], aq[0][kc], kf);
                mma_f16(s[0][1], aq[0][kc], kf + 2);
                mma_f16(s[1][0], aq[1][kc], kf);
                mma_f16(s[1][1], aq[1][kc], kf + 2);
            }

            unsigned pa[2][4];
#pragma unroll
            for (int mt = 0; mt < 2; mt++) {
#pragma unroll
                for (int j = 0; j < 2; j++) {
                    s[mt][j][0] = ex2(fmaf(s[mt][j][0], EXPC, li[mt][0]));
                    s[mt][j][1] = ex2(fmaf(s[mt][j][1], EXPC, li[mt][0]));
                    s[mt][j][2] = ex2(fmaf(s[mt][j][2], EXPC, li[mt][1]));
                    s[mt][j][3] = ex2(fmaf(s[mt][j][3], EXPC, li[mt][1]));
                }
                pa[mt][0] = packh2(s[mt][0][0], s[mt][0][1]);
                pa[mt][1] = packh2(s[mt][0][2], s[mt][0][3]);
                pa[mt][2] = packh2(s[mt][1][0], s[mt][1][1]);
                pa[mt][3] = packh2(s[mt][1][2], s[mt][1][3]);
                float* ap = attnBase + (long long)(mt * 16) * SS + t * 64 + ch * 16 + 2 * tg;
                asm volatile("st.global.cs.v2.f32 [%0], {%1,%2};"
                             :: "l"(ap), "f"(s[mt][0][0]), "f"(s[mt][0][1]));
                asm volatile("st.global.cs.v2.f32 [%0], {%1,%2};"
                             :: "l"(ap + 8), "f"(s[mt][1][0]), "f"(s[mt][1][1]));
                asm volatile("st.global.cs.v2.f32 [%0], {%1,%2};"
                             :: "l"(ap + 8LL * SS), "f"(s[mt][0][2]), "f"(s[mt][0][3]));
                asm volatile("st.global.cs.v2.f32 [%0], {%1,%2};"
                             :: "l"(ap + 8LL * SS + 8), "f"(s[mt][1][2]), "f"(s[mt][1][3]));
            }

#pragma unroll
            for (int np = 0; np < 4; np++) {
                unsigned vf[4];
                ldmx4(vf, vb + np * 2304 + ch * 32 + loff);
                mma_f16(o[0][2 * np],     pa[0], vf);
                mma_f16(o[0][2 * np + 1], pa[0], vf + 2);
                mma_f16(o[1][2 * np],     pa[1], vf);
                mma_f16(o[1][2 * np + 1], pa[1], vf + 2);
            }
        }
        if (++buf == 3) buf = 0;
    }

    __half* Cp = Cx + ((long long)b * SS + qt * 256 + wrow + g) * HH + h * HDD;
#pragma unroll
    for (int mt = 0; mt < 2; mt++)
#pragma unroll
        for (int nt = 0; nt < 8; nt++) {
            int col = nt * 8 + 2 * tg;
            *(__half2*)(Cp + (long long)(mt * 16) * HH + col) =
                __floats2half2_rn(o[mt][nt][0], o[mt][nt][1]);
            *(__half2*)(Cp + (long long)(mt * 16 + 8) * HH + col) =
                __floats2half2_rn(o[mt][nt][2], o[mt][nt][3]);
        }
}

// ---------------------------------------------------------------------------
extern "C" void kernel_launch(void* const* d_in, const int* in_sizes, int n_in,
                              void* d_out, int out_size)
{
    const float* query  = (const float*)d_in[0];
    const float* key_in = (const float*)d_in[1];
    const float* value  = (const float*)d_in[2];
    const float* Wq = (const float*)d_in[3];
    const float* bq = (const float*)d_in[4];
    const float* Wk = (const float*)d_in[5];
    const float* bk = (const float*)d_in[6];
    const float* Wv = (const float*)d_in[7];
    const float* bv = (const float*)d_in[8];
    const float* Wo = (const float*)d_in[9];
    const float* bo = (const float*)d_in[10];

    float* out  = (float*)d_out;
    float* attn = out + (long long)BSH;

    __half *Wh, *Qh, *Kh, *Vh, *Ch;
    cudaGetSymbolAddress((void**)&Wh, g_Wh);
    cudaGetSymbolAddress((void**)&Qh, g_Qh);
    cudaGetSymbolAddress((void**)&Kh, g_Kh);
    cudaGetSymbolAddress((void**)&Vh, g_Vh);
    cudaGetSymbolAddress((void**)&Ch, g_Ch);

    cudaFuncSetAttribute(attn_fused, cudaFuncAttributeMaxDynamicSharedMemorySize, F_SMEM);

    // weights fp32 -> fp16 (inputs converted inline inside qkv_gemm)
    cvt_w<<<dim3(256, 4), 256>>>(Wq, Wk, Wv, Wo, Wh);

    // merged Q/K/V projections
    qkv_gemm<<<dim3(4, 64, 3), 256>>>(query, key_in, value, Wh,
                                      bq, bk, bv, Qh, Kh, Vh);

    // fused attention (both passes, one kernel)
    attn_fused<<<dim3(SS / 256, BB * NHH), 256, F_SMEM>>>(Qh, Kh, Vh, attn, Ch);

    // output projection
    out_gemm<<<dim3(4, 64), 256>>>(Ch, Wh + 3u * HH * HH, bo, out);
}